// round 3
// baseline (speedup 1.0000x reference)
#include <cuda_runtime.h>
#include <math.h>

// Problem constants
#define B_      8
#define C_      512
#define K_      19
#define HW_     16384
#define NCHUNK  64            // pixel chunks per batch image (k1 grid = B_*NCHUNK)
#define PXC     256           // pixels per k1 block
#define TP      128           // pixels per k1 subtile (mask_s staging)

// Scratch (device globals — no allocation allowed)
__device__ float g_partial[B_ * NCHUNK * K_ * C_];   // ~19.9 MB partial class_feat
__device__ float g_cf[B_ * K_ * C_];                 // class_feat [b,k,c]
__device__ float g_filters[B_ * K_ * C_];            // filters    [b,k,c] (bias folded)

// -------------------------------------------------------------------------
// Kernel 1: fused  mask = sigmoid(Wm@x + bm)  and  partial class_feat = mask@x^T
// Grid: B_*NCHUNK blocks of 256 threads. Each block owns (batch b, 256 pixels).
// Phase A: 2 thread-groups of 128 (k 0..9 / k 10..18), one pixel per thread,
//          x loads coalesced over p, Wm via smem float4 broadcast.
// Phase B: thread owns a c-pair (512 c / 256 threads), all 19 k; mask via smem
//          float4 broadcast, x via per-thread float4 streaming (L2-hot).
// -------------------------------------------------------------------------

// Phase-A helper: compute NK pre-mask accumulators for k range [k0, k0+NK)
// for pixel p; write sigmoid to mask_s. Unconditional FMAs (NK compile-time).
template<int NK>
__device__ __forceinline__ void phaseA(const float* __restrict__ xb, int p,
                                       const float* __restrict__ Wm_s,
                                       const float* __restrict__ bm_s,
                                       int k0, float (*mask_s)[TP], int p_loc)
{
    float acc[NK];
    #pragma unroll
    for (int kk = 0; kk < NK; kk++) acc[kk] = bm_s[k0 + kk];

    for (int c = 0; c < C_; c += 4) {
        const float xv0 = xb[(size_t)(c + 0) * HW_ + p];
        const float xv1 = xb[(size_t)(c + 1) * HW_ + p];
        const float xv2 = xb[(size_t)(c + 2) * HW_ + p];
        const float xv3 = xb[(size_t)(c + 3) * HW_ + p];
        #pragma unroll
        for (int kk = 0; kk < NK; kk++) {
            const float4 w = *(const float4*)&Wm_s[(k0 + kk) * C_ + c];
            acc[kk] = fmaf(w.x, xv0, acc[kk]);
            acc[kk] = fmaf(w.y, xv1, acc[kk]);
            acc[kk] = fmaf(w.z, xv2, acc[kk]);
            acc[kk] = fmaf(w.w, xv3, acc[kk]);
        }
    }
    #pragma unroll
    for (int kk = 0; kk < NK; kk++)
        mask_s[k0 + kk][p_loc] = 1.0f / (1.0f + expf(-acc[kk]));
}

__global__ __launch_bounds__(256, 2)
void k1_mask_pool(const float* __restrict__ x,
                  const float* __restrict__ Wm,
                  const float* __restrict__ bm)
{
    __shared__ __align__(16) float Wm_s[K_ * C_];     // 38912 B
    __shared__ float bm_s[K_];
    __shared__ __align__(16) float mask_s[K_][TP];    // 9728 B

    const int t      = threadIdx.x;
    const int b      = blockIdx.x / NCHUNK;
    const int ch     = blockIdx.x % NCHUNK;
    const int p_base = ch * PXC;

    for (int i = t; i < K_ * C_; i += 256) Wm_s[i] = Wm[i];
    if (t < K_) bm_s[t] = bm[t];

    const float* xb = x + (size_t)b * C_ * HW_;

    // Phase A mapping
    const int p_loc = t & (TP - 1);
    const int kg    = t >> 7;          // 0 or 1

    // Phase B mapping: c-pair per thread
    const int c2 = t * 2;
    float accB[K_][2];
    #pragma unroll
    for (int k = 0; k < K_; k++) { accB[k][0] = 0.f; accB[k][1] = 0.f; }

    const float* xr0 = xb + (size_t)c2 * HW_ + p_base;
    const float* xr1 = xr0 + HW_;

    __syncthreads();

    #pragma unroll
    for (int st = 0; st < PXC / TP; st++) {
        // ---------------- Phase A: pre-mask for TP pixels ----------------
        const int p = p_base + st * TP + p_loc;
        if (kg == 0) phaseA<10>(xb, p, Wm_s, bm_s, 0,  mask_s, p_loc);
        else         phaseA<9 >(xb, p, Wm_s, bm_s, 10, mask_s, p_loc);
        __syncthreads();

        // ---------------- Phase B: accumulate class_feat partials --------
        const float* xa_p = xr0 + st * TP;
        const float* xc_p = xr1 + st * TP;
        for (int pp = 0; pp < TP; pp += 4) {
            const float4 xa = *(const float4*)(xa_p + pp);
            const float4 xc = *(const float4*)(xc_p + pp);
            #pragma unroll
            for (int k = 0; k < K_; k++) {
                const float4 m = *(const float4*)&mask_s[k][pp];
                accB[k][0] = fmaf(m.x, xa.x, accB[k][0]);
                accB[k][0] = fmaf(m.y, xa.y, accB[k][0]);
                accB[k][0] = fmaf(m.z, xa.z, accB[k][0]);
                accB[k][0] = fmaf(m.w, xa.w, accB[k][0]);
                accB[k][1] = fmaf(m.x, xc.x, accB[k][1]);
                accB[k][1] = fmaf(m.y, xc.y, accB[k][1]);
                accB[k][1] = fmaf(m.z, xc.z, accB[k][1]);
                accB[k][1] = fmaf(m.w, xc.w, accB[k][1]);
            }
        }
        __syncthreads();   // protect mask_s before next subtile's phase A
    }

    float* dst = g_partial + (size_t)(b * NCHUNK + ch) * K_ * C_;
    #pragma unroll
    for (int k = 0; k < K_; k++) {
        float2 v; v.x = accB[k][0]; v.y = accB[k][1];
        *(float2*)&dst[k * C_ + c2] = v;
    }
}

// -------------------------------------------------------------------------
// Kernel 2: deterministic reduction of partials -> class_feat / (h*w)
// Grid: B_*K_ blocks, 512 threads (thread = c). Fixed summation order.
// -------------------------------------------------------------------------
__global__ __launch_bounds__(512)
void k2_reduce()
{
    const int bk = blockIdx.x;
    const int c  = threadIdx.x;
    const int b  = bk / K_;
    const int k  = bk % K_;

    const float* src = g_partial + ((size_t)b * NCHUNK * K_ + k) * C_ + c;
    float s = 0.f;
    #pragma unroll 8
    for (int ch = 0; ch < NCHUNK; ch++)
        s += src[(size_t)ch * K_ * C_];
    g_cf[(b * K_ + k) * C_ + c] = s * (1.0f / (float)HW_);
}

// -------------------------------------------------------------------------
// Kernel 3: filters[b,k,o] = sum_c Wf[k,o,c] * cf[b,k,c] + bf[k,o]
// Grid: (K_, 4) blocks of 128 threads (thread = output channel within 128-slice).
// Wf is read exactly once total (~20 MB). cf staged transposed in smem,
// accessed warp-uniform (broadcast).
// -------------------------------------------------------------------------
__global__ __launch_bounds__(128)
void k3_filters(const float* __restrict__ Wf, const float* __restrict__ bf)
{
    __shared__ __align__(16) float cf_s[C_][B_];   // 16 KB

    const int k  = blockIdx.x;
    const int og = blockIdx.y;
    const int t  = threadIdx.x;

    for (int i = t; i < C_ * B_; i += 128) {
        const int c  = i >> 3;
        const int bb = i & 7;
        cf_s[c][bb] = g_cf[(bb * K_ + k) * C_ + c];
    }
    __syncthreads();

    const int o = og * 128 + t;
    const float* wrow = Wf + ((size_t)k * C_ + o) * C_;

    float acc[B_];
    #pragma unroll
    for (int bb = 0; bb < B_; bb++) acc[bb] = 0.f;

    for (int c = 0; c < C_; c += 4) {
        const float4 w = *(const float4*)(wrow + c);
        const float wv[4] = {w.x, w.y, w.z, w.w};
        #pragma unroll
        for (int j = 0; j < 4; j++) {
            const float4 f0 = *(const float4*)&cf_s[c + j][0];
            const float4 f1 = *(const float4*)&cf_s[c + j][4];
            acc[0] = fmaf(wv[j], f0.x, acc[0]);
            acc[1] = fmaf(wv[j], f0.y, acc[1]);
            acc[2] = fmaf(wv[j], f0.z, acc[2]);
            acc[3] = fmaf(wv[j], f0.w, acc[3]);
            acc[4] = fmaf(wv[j], f1.x, acc[4]);
            acc[5] = fmaf(wv[j], f1.y, acc[5]);
            acc[6] = fmaf(wv[j], f1.z, acc[6]);
            acc[7] = fmaf(wv[j], f1.w, acc[7]);
        }
    }

    const float bv = bf[k * C_ + o];
    #pragma unroll
    for (int bb = 0; bb < B_; bb++)
        g_filters[((size_t)bb * K_ + k) * C_ + o] = acc[bb] + bv;
}

// -------------------------------------------------------------------------
// Kernel 4: pred[b,k,p] = sum_c filters[b,k,c] * x[b,c,p]
// Grid: B_*64 blocks of 256 threads (thread = pixel, all 19 k in registers).
// filters staged in smem (float4 broadcast); x coalesced over p; stores
// coalesced over p per k.
// -------------------------------------------------------------------------
__global__ __launch_bounds__(256, 2)
void k4_pred(const float* __restrict__ x, float* __restrict__ out)
{
    __shared__ __align__(16) float f_s[K_ * C_];   // 38912 B

    const int t  = threadIdx.x;
    const int b  = blockIdx.x >> 6;          // /64
    const int pb = (blockIdx.x & 63) * 256;

    for (int i = t; i < K_ * C_; i += 256)
        f_s[i] = g_filters[(size_t)b * K_ * C_ + i];
    __syncthreads();

    const float* xb = x + (size_t)b * C_ * HW_;
    const int p = pb + t;

    float acc[K_];
    #pragma unroll
    for (int k = 0; k < K_; k++) acc[k] = 0.f;

    for (int c = 0; c < C_; c += 4) {
        const float xv0 = xb[(size_t)(c + 0) * HW_ + p];
        const float xv1 = xb[(size_t)(c + 1) * HW_ + p];
        const float xv2 = xb[(size_t)(c + 2) * HW_ + p];
        const float xv3 = xb[(size_t)(c + 3) * HW_ + p];
        #pragma unroll
        for (int k = 0; k < K_; k++) {
            const float4 w = *(const float4*)&f_s[k * C_ + c];
            acc[k] = fmaf(w.x, xv0, acc[k]);
            acc[k] = fmaf(w.y, xv1, acc[k]);
            acc[k] = fmaf(w.z, xv2, acc[k]);
            acc[k] = fmaf(w.w, xv3, acc[k]);
        }
    }

    float* ob = out + (size_t)b * K_ * HW_ + p;
    #pragma unroll
    for (int k = 0; k < K_; k++)
        ob[(size_t)k * HW_] = acc[k];
}

// -------------------------------------------------------------------------
extern "C" void kernel_launch(void* const* d_in, const int* in_sizes, int n_in,
                              void* d_out, int out_size)
{
    const float* x  = (const float*)d_in[0];
    const float* Wm = (const float*)d_in[1];
    const float* bm = (const float*)d_in[2];
    const float* Wf = (const float*)d_in[3];
    const float* bf = (const float*)d_in[4];
    float* out = (float*)d_out;

    k1_mask_pool<<<B_ * NCHUNK, 256>>>(x, Wm, bm);
    k2_reduce  <<<B_ * K_, 512>>>();
    k3_filters <<<dim3(K_, 4), 128>>>(Wf, bf);
    k4_pred    <<<B_ * 64, 256>>>(x, out);
}

// round 4
// speedup vs baseline: 1.4116x; 1.4116x over previous
#include <cuda_runtime.h>
#include <math.h>

#define B_      8
#define C_      512
#define K_      19
#define HW_     16384
#define NCHUNK  128           // px chunks per image for pooling partials
#define PXT     128           // pixels per k1b block
#define SLABW   518           // padded c-width of transposed x slab (bank-conflict-free)

typedef unsigned long long u64;

__device__ __forceinline__ u64 ffma2(u64 a, u64 b, u64 c) {
    u64 d; asm("fma.rn.f32x2 %0, %1, %2, %3;" : "=l"(d) : "l"(a), "l"(b), "l"(c)); return d;
}
__device__ __forceinline__ u64 pack2(float lo, float hi) {
    u64 d; asm("mov.b64 %0, {%1, %2};" : "=l"(d) : "f"(lo), "f"(hi)); return d;
}
__device__ __forceinline__ float2 unpack2(u64 v) {
    float2 r; asm("mov.b64 {%0, %1}, %2;" : "=f"(r.x), "=f"(r.y) : "l"(v)); return r;
}

// Scratch (device globals — no allocation allowed)
__device__ float g_mask[B_ * K_ * HW_];               // ~10 MB
__device__ float g_partial[B_ * NCHUNK * K_ * C_];    // ~39.8 MB
__device__ float g_cf[B_ * K_ * C_];
__device__ float g_filters[B_ * K_ * C_];

// -------------------------------------------------------------------------
// k1a: mask[b,k,p] = sigmoid(sum_c Wm[k,c] x[b,c,p] + bm[k])
// 256 blocks (b x 32 segs), 256 thr, 2 px/thread. FFMA2 over c-pairs.
// -------------------------------------------------------------------------
__global__ __launch_bounds__(256, 2)
void k1a_mask(const float* __restrict__ x,
              const float* __restrict__ Wm,
              const float* __restrict__ bm)
{
    __shared__ __align__(16) float Wm_s[K_ * C_];   // 38912 B
    __shared__ float bm_s[K_];

    const int t   = threadIdx.x;
    const int b   = blockIdx.x >> 5;
    const int seg = blockIdx.x & 31;
    const int p0  = seg * 512 + t * 2;

    for (int i = t; i < K_ * C_; i += 256) Wm_s[i] = Wm[i];
    if (t < K_) bm_s[t] = bm[t];

    const float* xb = x + (size_t)b * C_ * HW_ + p0;

    u64 acc[K_][2];
    #pragma unroll
    for (int k = 0; k < K_; k++) { acc[k][0] = 0ull; acc[k][1] = 0ull; }

    __syncthreads();

    #pragma unroll 2
    for (int c = 0; c < C_; c += 4) {
        const float2 x0 = *(const float2*)(xb + (size_t)(c + 0) * HW_);
        const float2 x1 = *(const float2*)(xb + (size_t)(c + 1) * HW_);
        const float2 x2 = *(const float2*)(xb + (size_t)(c + 2) * HW_);
        const float2 x3 = *(const float2*)(xb + (size_t)(c + 3) * HW_);
        const u64 a0 = pack2(x0.x, x1.x);   // px0, c-pair (c,c+1)
        const u64 b0 = pack2(x2.x, x3.x);   // px0, c-pair (c+2,c+3)
        const u64 a1 = pack2(x0.y, x1.y);   // px1
        const u64 b1 = pack2(x2.y, x3.y);
        #pragma unroll
        for (int k = 0; k < K_; k++) {
            const u64* w2 = (const u64*)&Wm_s[k * C_ + c];   // 16B aligned
            const u64 w01 = w2[0], w23 = w2[1];
            acc[k][0] = ffma2(a0, w01, acc[k][0]);
            acc[k][0] = ffma2(b0, w23, acc[k][0]);
            acc[k][1] = ffma2(a1, w01, acc[k][1]);
            acc[k][1] = ffma2(b1, w23, acc[k][1]);
        }
    }

    float* mb = g_mask + (size_t)b * K_ * HW_ + p0;
    #pragma unroll
    for (int k = 0; k < K_; k++) {
        const float2 f0 = unpack2(acc[k][0]);
        const float2 f1 = unpack2(acc[k][1]);
        const float s0 = f0.x + f0.y + bm_s[k];
        const float s1 = f1.x + f1.y + bm_s[k];
        float2 m;
        m.x = 1.0f / (1.0f + __expf(-s0));
        m.y = 1.0f / (1.0f + __expf(-s1));
        *(float2*)(mb + (size_t)k * HW_) = m;
    }
}

// -------------------------------------------------------------------------
// k1b: partial[b,ch,k,c] = sum_{p in chunk} mask[b,k,p] * x[b,c,p]
// 1024 blocks (b x 128 chunks of 128 px), 256 thr (thread = c-pair).
// x staged per 16-px slab into TRANSPOSED smem x_s[px][c] (pad 518):
//   coalesced global loads, conflict-free STS.32 and LDS.64.
// FFMA2 packs px-pairs; mask read as warp-uniform broadcast LDS.128.
// -------------------------------------------------------------------------
__global__ __launch_bounds__(256, 2)
void k1b_pool(const float* __restrict__ x)
{
    __shared__ __align__(16) float mask_s[K_][PXT];   // 9728 B
    __shared__ __align__(16) float x_s[16][SLABW];    // 33152 B

    const int t     = threadIdx.x;
    const int b     = blockIdx.x >> 7;
    const int ch    = blockIdx.x & 127;
    const int pbase = ch * PXT;
    const int c0    = t * 2;

    // stage mask tile (coalesced)
    for (int i = t; i < K_ * PXT; i += 256) {
        const int k  = i >> 7;
        const int pp = i & 127;
        mask_s[k][pp] = g_mask[((size_t)b * K_ + k) * HW_ + pbase + pp];
    }

    const float* xb = x + (size_t)b * C_ * HW_;

    u64 acc2[K_][2];
    #pragma unroll
    for (int k = 0; k < K_; k++) { acc2[k][0] = 0ull; acc2[k][1] = 0ull; }

    for (int pp0 = 0; pp0 < PXT; pp0 += 16) {
        // ---- stage x slab [512 c][16 px] transposed into x_s[px][c] ----
        #pragma unroll
        for (int it = 0; it < 8; it++) {
            const int idx = it * 256 + t;      // float4 index over (c, px-quad)
            const int c   = idx >> 2;
            const int q   = idx & 3;
            const float4 v = *(const float4*)&xb[(size_t)c * HW_ + pbase + pp0 + q * 4];
            x_s[q * 4 + 0][c] = v.x;
            x_s[q * 4 + 1][c] = v.y;
            x_s[q * 4 + 2][c] = v.z;
            x_s[q * 4 + 3][c] = v.w;
        }
        __syncthreads();

        // ---- compute: 4-px windows ----
        #pragma unroll
        for (int pw = 0; pw < 16; pw += 4) {
            const float2 xA = *(const float2*)&x_s[pw + 0][c0];
            const float2 xB = *(const float2*)&x_s[pw + 1][c0];
            const float2 xC = *(const float2*)&x_s[pw + 2][c0];
            const float2 xD = *(const float2*)&x_s[pw + 3][c0];
            const u64 p0a = pack2(xA.x, xB.x);   // c0, px-pair (pw,pw+1)
            const u64 p1a = pack2(xA.y, xB.y);   // c1
            const u64 p0b = pack2(xC.x, xD.x);   // c0, px-pair (pw+2,pw+3)
            const u64 p1b = pack2(xC.y, xD.y);
            const int ppm = pp0 + pw;
            #pragma unroll
            for (int k = 0; k < K_; k++) {
                const u64* m4 = (const u64*)&mask_s[k][ppm];   // 16B aligned, broadcast
                const u64 m01 = m4[0], m23 = m4[1];
                acc2[k][0] = ffma2(p0a, m01, acc2[k][0]);
                acc2[k][0] = ffma2(p0b, m23, acc2[k][0]);
                acc2[k][1] = ffma2(p1a, m01, acc2[k][1]);
                acc2[k][1] = ffma2(p1b, m23, acc2[k][1]);
            }
        }
        __syncthreads();   // protect x_s before next stage
    }

    float* dst = g_partial + (size_t)(b * NCHUNK + ch) * K_ * C_;
    #pragma unroll
    for (int k = 0; k < K_; k++) {
        const float2 f0 = unpack2(acc2[k][0]);
        const float2 f1 = unpack2(acc2[k][1]);
        float2 v; v.x = f0.x + f0.y; v.y = f1.x + f1.y;
        *(float2*)&dst[k * C_ + c0] = v;
    }
}

// -------------------------------------------------------------------------
// k2: deterministic reduction of partials -> class_feat / (h*w)
// -------------------------------------------------------------------------
__global__ __launch_bounds__(512)
void k2_reduce()
{
    const int bk = blockIdx.x;
    const int c  = threadIdx.x;
    const int b  = bk / K_;
    const int k  = bk % K_;

    const float* src = g_partial + ((size_t)b * NCHUNK * K_ + k) * C_ + c;
    float s = 0.f;
    #pragma unroll 8
    for (int ch = 0; ch < NCHUNK; ch++)
        s += src[(size_t)ch * K_ * C_];
    g_cf[(b * K_ + k) * C_ + c] = s * (1.0f / (float)HW_);
}

// -------------------------------------------------------------------------
// k3: filters[b,k,o] = sum_c Wf[k,o,c] * cf[b,k,c] + bf[k,o]
// -------------------------------------------------------------------------
__global__ __launch_bounds__(128)
void k3_filters(const float* __restrict__ Wf, const float* __restrict__ bf)
{
    __shared__ __align__(16) float cf_s[C_][B_];   // 16 KB

    const int k  = blockIdx.x;
    const int og = blockIdx.y;
    const int t  = threadIdx.x;

    for (int i = t; i < C_ * B_; i += 128) {
        const int c  = i >> 3;
        const int bb = i & 7;
        cf_s[c][bb] = g_cf[(bb * K_ + k) * C_ + c];
    }
    __syncthreads();

    const int o = og * 128 + t;
    const float* wrow = Wf + ((size_t)k * C_ + o) * C_;

    float acc[B_];
    #pragma unroll
    for (int bb = 0; bb < B_; bb++) acc[bb] = 0.f;

    #pragma unroll 2
    for (int c = 0; c < C_; c += 4) {
        const float4 w = *(const float4*)(wrow + c);
        const float wv[4] = {w.x, w.y, w.z, w.w};
        #pragma unroll
        for (int j = 0; j < 4; j++) {
            const float4 f0 = *(const float4*)&cf_s[c + j][0];
            const float4 f1 = *(const float4*)&cf_s[c + j][4];
            acc[0] = fmaf(wv[j], f0.x, acc[0]);
            acc[1] = fmaf(wv[j], f0.y, acc[1]);
            acc[2] = fmaf(wv[j], f0.z, acc[2]);
            acc[3] = fmaf(wv[j], f0.w, acc[3]);
            acc[4] = fmaf(wv[j], f1.x, acc[4]);
            acc[5] = fmaf(wv[j], f1.y, acc[5]);
            acc[6] = fmaf(wv[j], f1.z, acc[6]);
            acc[7] = fmaf(wv[j], f1.w, acc[7]);
        }
    }

    const float bv = bf[k * C_ + o];
    #pragma unroll
    for (int bb = 0; bb < B_; bb++)
        g_filters[((size_t)bb * K_ + k) * C_ + o] = acc[bb] + bv;
}

// -------------------------------------------------------------------------
// k4: pred[b,k,p] = sum_c filters[b,k,c] * x[b,c,p]
// 256 blocks (b x 32 segs), 256 thr, 2 px/thread. FFMA2 over c-pairs.
// -------------------------------------------------------------------------
__global__ __launch_bounds__(256, 2)
void k4_pred(const float* __restrict__ x, float* __restrict__ out)
{
    __shared__ __align__(16) float f_s[K_ * C_];   // 38912 B

    const int t   = threadIdx.x;
    const int b   = blockIdx.x >> 5;
    const int seg = blockIdx.x & 31;
    const int p0  = seg * 512 + t * 2;

    for (int i = t; i < K_ * C_; i += 256)
        f_s[i] = g_filters[(size_t)b * K_ * C_ + i];
    __syncthreads();

    const float* xb = x + (size_t)b * C_ * HW_ + p0;

    u64 acc[K_][2];
    #pragma unroll
    for (int k = 0; k < K_; k++) { acc[k][0] = 0ull; acc[k][1] = 0ull; }

    #pragma unroll 2
    for (int c = 0; c < C_; c += 4) {
        const float2 x0 = *(const float2*)(xb + (size_t)(c + 0) * HW_);
        const float2 x1 = *(const float2*)(xb + (size_t)(c + 1) * HW_);
        const float2 x2 = *(const float2*)(xb + (size_t)(c + 2) * HW_);
        const float2 x3 = *(const float2*)(xb + (size_t)(c + 3) * HW_);
        const u64 a0 = pack2(x0.x, x1.x);
        const u64 b0 = pack2(x2.x, x3.x);
        const u64 a1 = pack2(x0.y, x1.y);
        const u64 b1 = pack2(x2.y, x3.y);
        #pragma unroll
        for (int k = 0; k < K_; k++) {
            const u64* w2 = (const u64*)&f_s[k * C_ + c];
            const u64 w01 = w2[0], w23 = w2[1];
            acc[k][0] = ffma2(a0, w01, acc[k][0]);
            acc[k][0] = ffma2(b0, w23, acc[k][0]);
            acc[k][1] = ffma2(a1, w01, acc[k][1]);
            acc[k][1] = ffma2(b1, w23, acc[k][1]);
        }
    }

    float* ob = out + (size_t)b * K_ * HW_ + p0;
    #pragma unroll
    for (int k = 0; k < K_; k++) {
        const float2 f0 = unpack2(acc[k][0]);
        const float2 f1 = unpack2(acc[k][1]);
        float2 v; v.x = f0.x + f0.y; v.y = f1.x + f1.y;
        *(float2*)(ob + (size_t)k * HW_) = v;
    }
}

// -------------------------------------------------------------------------
extern "C" void kernel_launch(void* const* d_in, const int* in_sizes, int n_in,
                              void* d_out, int out_size)
{
    const float* x  = (const float*)d_in[0];
    const float* Wm = (const float*)d_in[1];
    const float* bm = (const float*)d_in[2];
    const float* Wf = (const float*)d_in[3];
    const float* bf = (const float*)d_in[4];
    float* out = (float*)d_out;

    k1a_mask  <<<B_ * 32, 256>>>(x, Wm, bm);
    k1b_pool  <<<B_ * NCHUNK, 256>>>(x);
    k2_reduce <<<B_ * K_, 512>>>();
    k3_filters<<<dim3(K_, 4), 128>>>(Wf, bf);
    k4_pred   <<<B_ * 32, 256>>>(x, out);
}

// round 5
// speedup vs baseline: 1.5257x; 1.0808x over previous
#include <cuda_runtime.h>
#include <math.h>

#define B_      8
#define C_      512
#define K_      19
#define HW_     16384
#define NCHUNK  128           // px chunks per image for pooling partials
#define PXT     128           // pixels per k1b block
#define SLABW   518           // padded c-width of transposed x slab (bank-conflict-free)

typedef unsigned long long u64;

__device__ __forceinline__ u64 ffma2(u64 a, u64 b, u64 c) {
    u64 d; asm("fma.rn.f32x2 %0, %1, %2, %3;" : "=l"(d) : "l"(a), "l"(b), "l"(c)); return d;
}
__device__ __forceinline__ u64 pack2(float lo, float hi) {
    u64 d; asm("mov.b64 %0, {%1, %2};" : "=l"(d) : "f"(lo), "f"(hi)); return d;
}
__device__ __forceinline__ float2 unpack2(u64 v) {
    float2 r; asm("mov.b64 {%0, %1}, %2;" : "=f"(r.x), "=f"(r.y) : "l"(v)); return r;
}

// Scratch (device globals — no allocation allowed)
__device__ float g_mask[B_ * K_ * HW_];               // ~10 MB
__device__ float g_partial[B_ * NCHUNK * K_ * C_];    // ~39.8 MB
__device__ float g_cf[B_ * K_ * C_];
__device__ float g_filters[B_ * K_ * C_];

// -------------------------------------------------------------------------
// k1a: mask[b,k,p] = sigmoid(sum_c Wm[k,c] x[b,c,p] + bm[k])
// 256 blocks (b x 32 segs), 256 thr, 2 px/thread. FFMA2 over c-pairs.
// Software-pipelined x loads (prefetch next 4 c-rows before FMA body).
// -------------------------------------------------------------------------
__global__ __launch_bounds__(256, 2)
void k1a_mask(const float* __restrict__ x,
              const float* __restrict__ Wm,
              const float* __restrict__ bm)
{
    __shared__ __align__(16) float Wm_s[K_ * C_];   // 38912 B
    __shared__ float bm_s[K_];

    const int t   = threadIdx.x;
    const int b   = blockIdx.x >> 5;
    const int seg = blockIdx.x & 31;
    const int p0  = seg * 512 + t * 2;

    for (int i = t; i < K_ * C_; i += 256) Wm_s[i] = Wm[i];
    if (t < K_) bm_s[t] = bm[t];

    const float* xp = x + (size_t)b * C_ * HW_ + p0;

    u64 acc[K_][2];
    #pragma unroll
    for (int k = 0; k < K_; k++) { acc[k][0] = 0ull; acc[k][1] = 0ull; }

    __syncthreads();

    float2 n0 = *(const float2*)(xp + (size_t)0 * HW_);
    float2 n1 = *(const float2*)(xp + (size_t)1 * HW_);
    float2 n2 = *(const float2*)(xp + (size_t)2 * HW_);
    float2 n3 = *(const float2*)(xp + (size_t)3 * HW_);

    #pragma unroll 2
    for (int c = 0; c < C_; c += 4) {
        const float2 x0 = n0, x1 = n1, x2 = n2, x3 = n3;
        const int cn = (c + 4 < C_) ? (c + 4) : c;   // clamped prefetch (tail re-read, unused)
        n0 = *(const float2*)(xp + (size_t)(cn + 0) * HW_);
        n1 = *(const float2*)(xp + (size_t)(cn + 1) * HW_);
        n2 = *(const float2*)(xp + (size_t)(cn + 2) * HW_);
        n3 = *(const float2*)(xp + (size_t)(cn + 3) * HW_);

        const u64 a0 = pack2(x0.x, x1.x);   // px0, c-pair (c,c+1)
        const u64 b0 = pack2(x2.x, x3.x);   // px0, c-pair (c+2,c+3)
        const u64 a1 = pack2(x0.y, x1.y);   // px1
        const u64 b1 = pack2(x2.y, x3.y);
        #pragma unroll
        for (int k = 0; k < K_; k++) {
            const ulonglong2 w = *(const ulonglong2*)&Wm_s[k * C_ + c];  // LDS.128 broadcast
            acc[k][0] = ffma2(a0, w.x, acc[k][0]);
            acc[k][0] = ffma2(b0, w.y, acc[k][0]);
            acc[k][1] = ffma2(a1, w.x, acc[k][1]);
            acc[k][1] = ffma2(b1, w.y, acc[k][1]);
        }
    }

    float* mb = g_mask + (size_t)b * K_ * HW_ + p0;
    #pragma unroll
    for (int k = 0; k < K_; k++) {
        const float2 f0 = unpack2(acc[k][0]);
        const float2 f1 = unpack2(acc[k][1]);
        const float s0 = f0.x + f0.y + bm_s[k];
        const float s1 = f1.x + f1.y + bm_s[k];
        float2 m;
        m.x = 1.0f / (1.0f + __expf(-s0));
        m.y = 1.0f / (1.0f + __expf(-s1));
        *(float2*)(mb + (size_t)k * HW_) = m;
    }
}

// -------------------------------------------------------------------------
// k1b: partial[b,ch,k,c] = sum_{p in chunk} mask[b,k,p] * x[b,c,p]
// 1024 blocks (b x 128 chunks of 128 px), 256 thr (thread = c-pair).
// x staged per 16-px slab into TRANSPOSED smem x_s[px][c] (pad 518):
//   coalesced global loads, conflict-free STS.32 and LDS.64.
// FFMA2 packs px-pairs; mask via warp-uniform broadcast LDS.128.
// -------------------------------------------------------------------------
__global__ __launch_bounds__(256, 2)
void k1b_pool(const float* __restrict__ x)
{
    __shared__ __align__(16) float mask_s[K_][PXT];   // 9728 B
    __shared__ __align__(16) float x_s[16][SLABW];    // 33152 B

    const int t     = threadIdx.x;
    const int b     = blockIdx.x >> 7;
    const int ch    = blockIdx.x & 127;
    const int pbase = ch * PXT;
    const int c0    = t * 2;

    // stage mask tile (coalesced)
    for (int i = t; i < K_ * PXT; i += 256) {
        const int k  = i >> 7;
        const int pp = i & 127;
        mask_s[k][pp] = g_mask[((size_t)b * K_ + k) * HW_ + pbase + pp];
    }

    const float* xb = x + (size_t)b * C_ * HW_;

    u64 acc2[K_][2];
    #pragma unroll
    for (int k = 0; k < K_; k++) { acc2[k][0] = 0ull; acc2[k][1] = 0ull; }

    for (int pp0 = 0; pp0 < PXT; pp0 += 16) {
        // ---- stage x slab [512 c][16 px] transposed into x_s[px][c] ----
        #pragma unroll
        for (int it = 0; it < 8; it++) {
            const int idx = it * 256 + t;      // float4 index over (c, px-quad)
            const int c   = idx >> 2;
            const int q   = idx & 3;
            const float4 v = *(const float4*)&xb[(size_t)c * HW_ + pbase + pp0 + q * 4];
            x_s[q * 4 + 0][c] = v.x;
            x_s[q * 4 + 1][c] = v.y;
            x_s[q * 4 + 2][c] = v.z;
            x_s[q * 4 + 3][c] = v.w;
        }
        __syncthreads();

        // ---- compute: 4-px windows ----
        #pragma unroll
        for (int pw = 0; pw < 16; pw += 4) {
            const float2 xA = *(const float2*)&x_s[pw + 0][c0];
            const float2 xB = *(const float2*)&x_s[pw + 1][c0];
            const float2 xC = *(const float2*)&x_s[pw + 2][c0];
            const float2 xD = *(const float2*)&x_s[pw + 3][c0];
            const u64 p0a = pack2(xA.x, xB.x);   // c0, px-pair (pw,pw+1)
            const u64 p1a = pack2(xA.y, xB.y);   // c1
            const u64 p0b = pack2(xC.x, xD.x);   // c0, px-pair (pw+2,pw+3)
            const u64 p1b = pack2(xC.y, xD.y);
            const int ppm = pp0 + pw;
            #pragma unroll
            for (int k = 0; k < K_; k++) {
                const ulonglong2 m = *(const ulonglong2*)&mask_s[k][ppm];  // LDS.128 broadcast
                acc2[k][0] = ffma2(p0a, m.x, acc2[k][0]);
                acc2[k][0] = ffma2(p0b, m.y, acc2[k][0]);
                acc2[k][1] = ffma2(p1a, m.x, acc2[k][1]);
                acc2[k][1] = ffma2(p1b, m.y, acc2[k][1]);
            }
        }
        __syncthreads();   // protect x_s before next stage
    }

    float* dst = g_partial + (size_t)(b * NCHUNK + ch) * K_ * C_;
    #pragma unroll
    for (int k = 0; k < K_; k++) {
        const float2 f0 = unpack2(acc2[k][0]);
        const float2 f1 = unpack2(acc2[k][1]);
        float2 v; v.x = f0.x + f0.y; v.y = f1.x + f1.y;
        *(float2*)&dst[k * C_ + c0] = v;
    }
}

// -------------------------------------------------------------------------
// k2: deterministic reduction of partials -> class_feat / (h*w)
// -------------------------------------------------------------------------
__global__ __launch_bounds__(512)
void k2_reduce()
{
    const int bk = blockIdx.x;
    const int c  = threadIdx.x;
    const int b  = bk / K_;
    const int k  = bk % K_;

    const float* src = g_partial + ((size_t)b * NCHUNK * K_ + k) * C_ + c;
    float s = 0.f;
    #pragma unroll 8
    for (int ch = 0; ch < NCHUNK; ch++)
        s += src[(size_t)ch * K_ * C_];
    g_cf[(b * K_ + k) * C_ + c] = s * (1.0f / (float)HW_);
}

// -------------------------------------------------------------------------
// k3: filters[b,k,o] = sum_c Wf[k,o,c] * cf[b,k,c] + bf[k,o]
// Grid (K_, 16) = 304 blocks, 256 thr. Warp w owns c-chunk [w*64, w*64+64),
// lane owns o (32 o's per block) -> cf_s reads are pure broadcast,
// Wf walked with unroll-16 float4 (16 LDG.128 in flight / thread).
// Deterministic cross-warp reduce via smem.
// -------------------------------------------------------------------------
__global__ __launch_bounds__(256)
void k3_filters(const float* __restrict__ Wf, const float* __restrict__ bf)
{
    __shared__ __align__(16) float cf_s[C_][B_];        // 16 KB
    __shared__ __align__(16) float red_s[8][32][B_];    // 8 KB

    const int k  = blockIdx.x;
    const int og = blockIdx.y;
    const int t  = threadIdx.x;
    const int w  = t >> 5;          // warp = c-chunk
    const int ol = t & 31;          // lane = o within group
    const int o  = og * 32 + ol;

    for (int i = t; i < C_ * B_; i += 256) {
        const int c  = i >> 3;
        const int bb = i & 7;
        cf_s[c][bb] = g_cf[(bb * K_ + k) * C_ + c];
    }
    __syncthreads();

    const float* wrow = Wf + ((size_t)k * C_ + o) * C_ + w * 64;

    float acc[B_];
    #pragma unroll
    for (int bb = 0; bb < B_; bb++) acc[bb] = 0.f;

    #pragma unroll
    for (int i = 0; i < 16; i++) {                  // 64 c per warp, float4 steps
        const int c = w * 64 + i * 4;
        const float4 wv4 = *(const float4*)(wrow + i * 4);
        const float wv[4] = {wv4.x, wv4.y, wv4.z, wv4.w};
        #pragma unroll
        for (int j = 0; j < 4; j++) {
            const float4 f0 = *(const float4*)&cf_s[c + j][0];   // broadcast
            const float4 f1 = *(const float4*)&cf_s[c + j][4];
            acc[0] = fmaf(wv[j], f0.x, acc[0]);
            acc[1] = fmaf(wv[j], f0.y, acc[1]);
            acc[2] = fmaf(wv[j], f0.z, acc[2]);
            acc[3] = fmaf(wv[j], f0.w, acc[3]);
            acc[4] = fmaf(wv[j], f1.x, acc[4]);
            acc[5] = fmaf(wv[j], f1.y, acc[5]);
            acc[6] = fmaf(wv[j], f1.z, acc[6]);
            acc[7] = fmaf(wv[j], f1.w, acc[7]);
        }
    }

    #pragma unroll
    for (int bb = 0; bb < B_; bb++) red_s[w][ol][bb] = acc[bb];
    __syncthreads();

    // final: 256 threads = 32 o x 8 b; fixed summation order over warps
    {
        const int oo = t & 31;
        const int bb = t >> 5;
        float s = 0.f;
        #pragma unroll
        for (int ww = 0; ww < 8; ww++) s += red_s[ww][oo][bb];
        const int oglob = og * 32 + oo;
        g_filters[((size_t)bb * K_ + k) * C_ + oglob] = s + bf[k * C_ + oglob];
    }
}

// -------------------------------------------------------------------------
// k4: pred[b,k,p] = sum_c filters[b,k,c] * x[b,c,p]
// 256 blocks (b x 32 segs), 256 thr, 2 px/thread, pipelined like k1a.
// -------------------------------------------------------------------------
__global__ __launch_bounds__(256, 2)
void k4_pred(const float* __restrict__ x, float* __restrict__ out)
{
    __shared__ __align__(16) float f_s[K_ * C_];   // 38912 B

    const int t   = threadIdx.x;
    const int b   = blockIdx.x >> 5;
    const int seg = blockIdx.x & 31;
    const int p0  = seg * 512 + t * 2;

    for (int i = t; i < K_ * C_; i += 256)
        f_s[i] = g_filters[(size_t)b * K_ * C_ + i];

    const float* xp = x + (size_t)b * C_ * HW_ + p0;

    u64 acc[K_][2];
    #pragma unroll
    for (int k = 0; k < K_; k++) { acc[k][0] = 0ull; acc[k][1] = 0ull; }

    __syncthreads();

    float2 n0 = *(const float2*)(xp + (size_t)0 * HW_);
    float2 n1 = *(const float2*)(xp + (size_t)1 * HW_);
    float2 n2 = *(const float2*)(xp + (size_t)2 * HW_);
    float2 n3 = *(const float2*)(xp + (size_t)3 * HW_);

    #pragma unroll 2
    for (int c = 0; c < C_; c += 4) {
        const float2 x0 = n0, x1 = n1, x2 = n2, x3 = n3;
        const int cn = (c + 4 < C_) ? (c + 4) : c;
        n0 = *(const float2*)(xp + (size_t)(cn + 0) * HW_);
        n1 = *(const float2*)(xp + (size_t)(cn + 1) * HW_);
        n2 = *(const float2*)(xp + (size_t)(cn + 2) * HW_);
        n3 = *(const float2*)(xp + (size_t)(cn + 3) * HW_);

        const u64 a0 = pack2(x0.x, x1.x);
        const u64 b0 = pack2(x2.x, x3.x);
        const u64 a1 = pack2(x0.y, x1.y);
        const u64 b1 = pack2(x2.y, x3.y);
        #pragma unroll
        for (int k = 0; k < K_; k++) {
            const ulonglong2 w = *(const ulonglong2*)&f_s[k * C_ + c];
            acc[k][0] = ffma2(a0, w.x, acc[k][0]);
            acc[k][0] = ffma2(b0, w.y, acc[k][0]);
            acc[k][1] = ffma2(a1, w.x, acc[k][1]);
            acc[k][1] = ffma2(b1, w.y, acc[k][1]);
        }
    }

    float* ob = out + (size_t)b * K_ * HW_ + p0;
    #pragma unroll
    for (int k = 0; k < K_; k++) {
        const float2 f0 = unpack2(acc[k][0]);
        const float2 f1 = unpack2(acc[k][1]);
        float2 v; v.x = f0.x + f0.y; v.y = f1.x + f1.y;
        *(float2*)(ob + (size_t)k * HW_) = v;
    }
}

// -------------------------------------------------------------------------
extern "C" void kernel_launch(void* const* d_in, const int* in_sizes, int n_in,
                              void* d_out, int out_size)
{
    const float* x  = (const float*)d_in[0];
    const float* Wm = (const float*)d_in[1];
    const float* bm = (const float*)d_in[2];
    const float* Wf = (const float*)d_in[3];
    const float* bf = (const float*)d_in[4];
    float* out = (float*)d_out;

    k1a_mask  <<<B_ * 32, 256>>>(x, Wm, bm);
    k1b_pool  <<<B_ * NCHUNK, 256>>>(x);
    k2_reduce <<<B_ * K_, 512>>>();
    k3_filters<<<dim3(K_, 16), 256>>>(Wf, bf);
    k4_pred   <<<B_ * 32, 256>>>(x, out);
}